// round 15
// baseline (speedup 1.0000x reference)
#include <cuda_runtime.h>
#include <cuda_fp16.h>

#define NN 50000
#define D 128
#define EE 800000
#define PREP_BLOCKS 592   // 4 blocks/SM x 148 SMs: co-residency guaranteed

typedef unsigned long long ull;

// Scratch (device globals: allocation-free; zero-initialized at module load;
// kernels restore zero-state after last use so graph replays see identical
// initial conditions).
__device__ __align__(16) __half g_h[NN * D];    // fp16 features (both layers)
__device__ __align__(16) float g_x1[NN * D];    // layer-1 activations (f32)
__device__ float g_deg[NN];
__device__ float g_dinv[NN];
__device__ int   g_cnt[NN];
__device__ int   g_cur[NN];
__device__ int   g_off[NN];                     // segment start (unordered)
__device__ int   g_total;                       // segment allocator
__device__ int   g_csr_src[EE];
__device__ float g_csr_coef[EE];
// software grid barrier state (sense-reversing: phase increments persist)
__device__ volatile unsigned g_barNum = 0;
__device__ volatile unsigned g_barPhase = 0;

// ---- packed f32x2 helpers (sm_103a) ---------------------------------------
__device__ __forceinline__ ull pk2(float a) {
    ull r; asm("mov.b64 %0, {%1, %1};" : "=l"(r) : "f"(a)); return r;
}
__device__ __forceinline__ ull pkf2(float2 a) {
    ull r; asm("mov.b64 %0, {%1, %2};" : "=l"(r) : "f"(a.x), "f"(a.y)); return r;
}
__device__ __forceinline__ void fma2(ull& d, ull a, ull b) {
    asm("fma.rn.f32x2 %0, %1, %2, %0;" : "+l"(d) : "l"(a), "l"(b));
}
__device__ __forceinline__ float2 unpk(ull a) {
    float2 r; asm("mov.b64 {%0, %1}, %2;" : "=f"(r.x), "=f"(r.y) : "l"(a)); return r;
}

// fp16x4 (one ull) -> two packed f32x2 operands
__device__ __forceinline__ void h4_to_f2x2(ull h, ull& lo, ull& hi) {
    unsigned int ulo = (unsigned int)h;
    unsigned int uhi = (unsigned int)(h >> 32);
    float2 flo = __half22float2(*reinterpret_cast<__half2*>(&ulo));
    float2 fhi = __half22float2(*reinterpret_cast<__half2*>(&uhi));
    lo = pkf2(flo);
    hi = pkf2(fhi);
}

// ---------------------------------------------------------------------------
// Software grid barrier (all PREP_BLOCKS co-resident by construction).
// ---------------------------------------------------------------------------
__device__ __forceinline__ void grid_bar() {
    __syncthreads();
    if (threadIdx.x == 0) {
        unsigned ph = g_barPhase;
        __threadfence();
        unsigned arr = atomicAdd((unsigned*)&g_barNum, 1u);
        if (arr == gridDim.x - 1) {
            g_barNum = 0;
            __threadfence();
            g_barPhase = ph + 1;
        } else {
            while (g_barPhase == ph) __nanosleep(64);
        }
    }
    __syncthreads();
}

// ---------------------------------------------------------------------------
// FUSED prep: hist -> gbar -> offsets/dinv -> gbar -> scatter. One launch.
// edge_index is int32 on this dataset (proven: int64 read faulted, int32
// passes); bounds guards keep any surprise non-UB.
// ---------------------------------------------------------------------------
__global__ void __launch_bounds__(256, 4)
prep_kernel(const int* __restrict__ ei, const float* __restrict__ ew,
            int E, int n) {
    int gtid = blockIdx.x * blockDim.x + threadIdx.x;
    int gstride = gridDim.x * blockDim.x;

    // Phase A: degree accumulate + dst histogram
    for (int e = gtid; e < E; e += gstride) {
        int d = ei[E + e];
        if ((unsigned)d < (unsigned)n) {
            atomicAdd(&g_deg[d], ew[e]);
            atomicAdd(&g_cnt[d], 1);
        }
    }
    grid_bar();

    // Phase B: segment allocation + dinv (self-loop folded); reset g_deg
    for (int i = gtid; i < n; i += gstride) {
        g_off[i] = atomicAdd(&g_total, g_cnt[i]);
        g_dinv[i] = rsqrtf(g_deg[i] + 1.0f);
        g_deg[i] = 0.0f;
    }
    grid_bar();

    // Phase C: counting-sort scatter with precomputed coef
    for (int e = gtid; e < E; e += gstride) {
        int s = ei[e];
        int d = ei[E + e];
        if ((unsigned)s < (unsigned)n && (unsigned)d < (unsigned)n) {
            int pos = g_off[d] + atomicAdd(&g_cur[d], 1);
            g_csr_src[pos] = s;
            g_csr_coef[pos] = g_dinv[s] * ew[e] * g_dinv[d];
        }
    }
}

// ---------------------------------------------------------------------------
// GEMM (measured-best): block 128 threads, 16 nodes, transposed smem tile.
// ---------------------------------------------------------------------------
__global__ void gemm_kernel(const float* __restrict__ X,
                            const float* __restrict__ W, int n) {
    __shared__ float xsT[D][20];  // [k][node], padded stride
    int node0 = blockIdx.x * 16;
    int t = threadIdx.x;

#pragma unroll
    for (int r = 0; r < 16; r++) {
        float v = (node0 + r < n) ? __ldg(X + (size_t)(node0 + r) * D + t) : 0.f;
        xsT[t][r] = v;
    }
    __syncthreads();

    int tx = t & 31;
    int tg = t >> 5;

    ull acc[4][2];
#pragma unroll
    for (int i = 0; i < 4; i++) { acc[i][0] = 0ull; acc[i][1] = 0ull; }

#pragma unroll 2
    for (int k = 0; k < D; k++) {
        longlong2 w2 = __ldg((const longlong2*)W + (size_t)k * 32 + tx);
        float4 xv = *(const float4*)&xsT[k][tg * 4];  // broadcast LDS.128
        ull wlo = (ull)w2.x, whi = (ull)w2.y;
        ull xp;
        xp = pk2(xv.x); fma2(acc[0][0], xp, wlo); fma2(acc[0][1], xp, whi);
        xp = pk2(xv.y); fma2(acc[1][0], xp, wlo); fma2(acc[1][1], xp, whi);
        xp = pk2(xv.z); fma2(acc[2][0], xp, wlo); fma2(acc[2][1], xp, whi);
        xp = pk2(xv.w); fma2(acc[3][0], xp, wlo); fma2(acc[3][1], xp, whi);
    }

#pragma unroll
    for (int i = 0; i < 4; i++) {
        int node = node0 + tg * 4 + i;
        if (node < n) {
            float2 p0 = unpk(acc[i][0]);
            float2 p1 = unpk(acc[i][1]);
            __half2 h0 = __floats2half2_rn(p0.x, p0.y);
            __half2 h1 = __floats2half2_rn(p1.x, p1.y);
            uint2 v;
            v.x = *reinterpret_cast<unsigned int*>(&h0);
            v.y = *reinterpret_cast<unsigned int*>(&h1);
            ((uint2*)(g_h + (size_t)node * D))[tx] = v;
        }
    }
}

// ---------------------------------------------------------------------------
// Pull aggregation (R10 measured-best, verbatim): warp per dst node,
// lane owns 4 dims; fp16 gather, f32x2 accumulate, unroll 2.
// ---------------------------------------------------------------------------
__device__ __forceinline__ void agg_core(int node, int lane, ull& a0, ull& a1) {
    int beg = g_off[node];
    int end = beg + g_cnt[node];
    const ull* hv = (const ull*)g_h;

    int j = beg;
    for (; j + 1 < end; j += 2) {
        int s0 = __ldg(&g_csr_src[j]);
        int s1 = __ldg(&g_csr_src[j + 1]);
        float c0 = __ldg(&g_csr_coef[j]);
        float c1 = __ldg(&g_csr_coef[j + 1]);
        ull h0 = __ldg(hv + (size_t)s0 * 32 + lane);
        ull h1 = __ldg(hv + (size_t)s1 * 32 + lane);
        ull l0, u0, l1, u1;
        h4_to_f2x2(h0, l0, u0);
        h4_to_f2x2(h1, l1, u1);
        ull cp0 = pk2(c0), cp1 = pk2(c1);
        fma2(a0, cp0, l0); fma2(a1, cp0, u0);
        fma2(a0, cp1, l1); fma2(a1, cp1, u1);
    }
    if (j < end) {
        int s0 = __ldg(&g_csr_src[j]);
        float c0 = __ldg(&g_csr_coef[j]);
        ull h0 = __ldg(hv + (size_t)s0 * 32 + lane);
        ull l0, u0;
        h4_to_f2x2(h0, l0, u0);
        ull cp0 = pk2(c0);
        fma2(a0, cp0, l0); fma2(a1, cp0, u0);
    }

    // self-loop: + dinv^2 * h[node]
    float sl = g_dinv[node];
    ull slp = pk2(sl * sl);
    ull hs = hv[(size_t)node * 32 + lane];
    ull ls, us;
    h4_to_f2x2(hs, ls, us);
    fma2(a0, slp, ls); fma2(a1, slp, us);
}

__global__ void agg1_kernel(const float* __restrict__ b, int n) {
    int node = blockIdx.x * 8 + (threadIdx.x >> 5);
    int lane = threadIdx.x & 31;
    if (node >= n) return;

    ull a0 = 0ull, a1 = 0ull;
    agg_core(node, lane, a0, a1);

    if (lane == 0) g_cur[node] = 0;   // restore zero-state (last use: scatter)

    float2 p0 = unpk(a0), p1 = unpk(a1);
    float4 bias = __ldg((const float4*)b + lane);
    float4 v;
    v.x = fmaxf(p0.x + bias.x, 0.f);
    v.y = fmaxf(p0.y + bias.y, 0.f);
    v.z = fmaxf(p1.x + bias.z, 0.f);
    v.w = fmaxf(p1.y + bias.w, 0.f);
    ((float4*)g_x1)[(size_t)node * 32 + lane] = v;
}

__global__ void agg2_kernel(const float* __restrict__ b,
                            float* __restrict__ out, int n) {
    int node = blockIdx.x * 8 + (threadIdx.x >> 5);
    int lane = threadIdx.x & 31;
    if (node >= n) return;

    ull a0 = 0ull, a1 = 0ull;
    agg_core(node, lane, a0, a1);

    if (lane == 0) {
        g_cnt[node] = 0;              // restore zero-state
        if (node == 0) g_total = 0;
    }

    float2 p0 = unpk(a0), p1 = unpk(a1);
    float4 bias = __ldg((const float4*)b + lane);
    float4 v2;
    v2.x = fmaxf(p0.x + bias.x, 0.f);
    v2.y = fmaxf(p0.y + bias.y, 0.f);
    v2.z = fmaxf(p1.x + bias.z, 0.f);
    v2.w = fmaxf(p1.y + bias.w, 0.f);

    float4 v1 = ((const float4*)g_x1)[(size_t)node * 32 + lane];
    float4 lo = make_float4(v1.x, v2.x, v1.y, v2.y);
    float4 hi = make_float4(v1.z, v2.z, v1.w, v2.w);
    size_t o = (size_t)node * 64 + (size_t)lane * 2;
    ((float4*)out)[o] = lo;
    ((float4*)out)[o + 1] = hi;
}

// ---------------------------------------------------------------------------
extern "C" void kernel_launch(void* const* d_in, const int* in_sizes, int n_in,
                              void* d_out, int out_size) {
    const float* x = (const float*)d_in[0];
    const int* ei = (const int*)d_in[1];   // int32 edge_index (proven)
    const float* ew = (const float*)d_in[2];
    const float* W1 = (const float*)d_in[3];
    const float* b1 = (const float*)d_in[4];
    const float* W2 = (const float*)d_in[5];
    const float* b2 = (const float*)d_in[6];
    float* out = (float*)d_out;

    int n = in_sizes[0] / D;   // 50000
    int E = in_sizes[2];       // 800000

    static cudaStream_t s2 = nullptr;
    static cudaEvent_t evRoot = nullptr, evPrep = nullptr;
    static const float* x1_ptr = nullptr;
    if (!s2) {
        cudaStreamCreateWithFlags(&s2, cudaStreamNonBlocking);
        cudaEventCreateWithFlags(&evRoot, cudaEventDisableTiming);
        cudaEventCreateWithFlags(&evPrep, cudaEventDisableTiming);
        void* p = nullptr;
        cudaGetSymbolAddress(&p, g_x1);
        x1_ptr = (const float*)p;
    }

    int gemmBlocks = (n + 15) / 16;
    int aggBlocks = (n + 7) / 8;

    // Fork point
    cudaEventRecord(evRoot, 0);

    // [1] fused prep on s2 (concurrent with GEMM1)
    cudaStreamWaitEvent(s2, evRoot, 0);
    prep_kernel<<<PREP_BLOCKS, 256, 0, s2>>>(ei, ew, E, n);
    cudaEventRecord(evPrep, s2);

    // [2] GEMM1 on default stream
    gemm_kernel<<<gemmBlocks, 128>>>(x, W1, n);

    // Join, then sequential main path: [3] agg1, [4] gemm2, [5] agg2
    cudaStreamWaitEvent(0, evPrep, 0);
    agg1_kernel<<<aggBlocks, 256>>>(b1, n);
    gemm_kernel<<<gemmBlocks, 128>>>(x1_ptr, W2, n);
    agg2_kernel<<<aggBlocks, 256>>>(b2, out, n);
}

// round 16
// speedup vs baseline: 1.0561x; 1.0561x over previous
#include <cuda_runtime.h>
#include <cuda_fp16.h>

#define NN 50000
#define D 128
#define EE 800000

typedef unsigned long long ull;

// Scratch (device globals: allocation-free; zero-initialized at module load;
// kernels restore zero-state after last use so graph replays see identical
// initial conditions).
__device__ __align__(16) __half g_h[NN * D];    // fp16 features (both layers)
__device__ __align__(16) float g_x1[NN * D];    // layer-1 activations (f32)
__device__ float g_deg[NN];
__device__ float g_dinv[NN];
__device__ int   g_cnt[NN];
__device__ int   g_cur[NN];
__device__ int   g_off[NN];                     // segment start (unordered)
__device__ int   g_total;                       // segment allocator
__device__ int   g_csr_src[EE];
__device__ float g_csr_coef[EE];

// ---- packed f32x2 helpers (sm_103a) ---------------------------------------
__device__ __forceinline__ ull pk2(float a) {
    ull r; asm("mov.b64 %0, {%1, %1};" : "=l"(r) : "f"(a)); return r;
}
__device__ __forceinline__ ull pkf2(float2 a) {
    ull r; asm("mov.b64 %0, {%1, %2};" : "=l"(r) : "f"(a.x), "f"(a.y)); return r;
}
__device__ __forceinline__ void fma2(ull& d, ull a, ull b) {
    asm("fma.rn.f32x2 %0, %1, %2, %0;" : "+l"(d) : "l"(a), "l"(b));
}
__device__ __forceinline__ float2 unpk(ull a) {
    float2 r; asm("mov.b64 {%0, %1}, %2;" : "=f"(r.x), "=f"(r.y) : "l"(a)); return r;
}

// fp16x4 (one ull) -> two packed f32x2 operands
__device__ __forceinline__ void h4_to_f2x2(ull h, ull& lo, ull& hi) {
    unsigned int ulo = (unsigned int)h;
    unsigned int uhi = (unsigned int)(h >> 32);
    float2 flo = __half22float2(*reinterpret_cast<__half2*>(&ulo));
    float2 fhi = __half22float2(*reinterpret_cast<__half2*>(&uhi));
    lo = pkf2(flo);
    hi = pkf2(fhi);
}

// ---------------------------------------------------------------------------
// Prep (R10 structure; int32 edges hardcoded — proven in R14/15; guards keep
// any surprise non-UB).
// ---------------------------------------------------------------------------
__global__ void deg_hist_kernel(const int* __restrict__ ei,
                                const float* __restrict__ ew, int E, int n) {
    int e = blockIdx.x * blockDim.x + threadIdx.x;
    if (e < E) {
        int d = ei[E + e];
        if ((unsigned)d >= (unsigned)n) return;
        atomicAdd(&g_deg[d], ew[e]);
        atomicAdd(&g_cnt[d], 1);
    }
}

// segment allocation + dinv (self-loop folded: deg_sum + 1); resets g_deg.
__global__ void offsets_kernel(int n) {
    int i = blockIdx.x * blockDim.x + threadIdx.x;
    if (i < n) {
        int cnt = g_cnt[i];
        g_off[i] = atomicAdd(&g_total, cnt);
        g_dinv[i] = rsqrtf(g_deg[i] + 1.0f);
        g_deg[i] = 0.0f;
    }
}

// counting-sort scatter with precomputed coef
__global__ void scatter_kernel(const int* __restrict__ ei,
                               const float* __restrict__ ew, int E, int n) {
    int e = blockIdx.x * blockDim.x + threadIdx.x;
    if (e < E) {
        int s = ei[e];
        int d = ei[E + e];
        if ((unsigned)s >= (unsigned)n || (unsigned)d >= (unsigned)n) return;
        int pos = g_off[d] + atomicAdd(&g_cur[d], 1);
        g_csr_src[pos] = s;
        g_csr_coef[pos] = g_dinv[s] * ew[e] * g_dinv[d];
    }
}

// ---------------------------------------------------------------------------
// GEMM: block 128 threads, 32 nodes; warp handles 8 nodes via TWO broadcast
// LDS.128 per k. W LDG.128 per k amortized over 8 nodes (was 4): L1
// wavefronts/node drop 40% (profile: L1 60.7% was the binding pipe).
// xsT stride 40 floats = 160B: 16B-aligned rows, conflict-free broadcasts.
// ---------------------------------------------------------------------------
__global__ void gemm_kernel(const float* __restrict__ X,
                            const float* __restrict__ W, int n) {
    __shared__ float xsT[D][40];  // [k][node 0..31] + pad
    int node0 = blockIdx.x * 32;
    int t = threadIdx.x;          // t = feature column k for the fill

#pragma unroll 4
    for (int r = 0; r < 32; r++) {
        float v = (node0 + r < n) ? __ldg(X + (size_t)(node0 + r) * D + t) : 0.f;
        xsT[t][r] = v;
    }
    __syncthreads();

    int tx = t & 31;   // owns dims [4tx, 4tx+4)
    int tg = t >> 5;   // owns nodes [8tg, 8tg+8)

    ull acc[8][2];
#pragma unroll
    for (int i = 0; i < 8; i++) { acc[i][0] = 0ull; acc[i][1] = 0ull; }

#pragma unroll 2
    for (int k = 0; k < D; k++) {
        longlong2 w2 = __ldg((const longlong2*)W + (size_t)k * 32 + tx);
        float4 xa = *(const float4*)&xsT[k][tg * 8];      // broadcast LDS.128
        float4 xb = *(const float4*)&xsT[k][tg * 8 + 4];  // broadcast LDS.128
        ull wlo = (ull)w2.x, whi = (ull)w2.y;
        ull xp;
        xp = pk2(xa.x); fma2(acc[0][0], xp, wlo); fma2(acc[0][1], xp, whi);
        xp = pk2(xa.y); fma2(acc[1][0], xp, wlo); fma2(acc[1][1], xp, whi);
        xp = pk2(xa.z); fma2(acc[2][0], xp, wlo); fma2(acc[2][1], xp, whi);
        xp = pk2(xa.w); fma2(acc[3][0], xp, wlo); fma2(acc[3][1], xp, whi);
        xp = pk2(xb.x); fma2(acc[4][0], xp, wlo); fma2(acc[4][1], xp, whi);
        xp = pk2(xb.y); fma2(acc[5][0], xp, wlo); fma2(acc[5][1], xp, whi);
        xp = pk2(xb.z); fma2(acc[6][0], xp, wlo); fma2(acc[6][1], xp, whi);
        xp = pk2(xb.w); fma2(acc[7][0], xp, wlo); fma2(acc[7][1], xp, whi);
    }

#pragma unroll
    for (int i = 0; i < 8; i++) {
        int node = node0 + tg * 8 + i;
        if (node < n) {
            float2 p0 = unpk(acc[i][0]);
            float2 p1 = unpk(acc[i][1]);
            __half2 h0 = __floats2half2_rn(p0.x, p0.y);
            __half2 h1 = __floats2half2_rn(p1.x, p1.y);
            uint2 v;
            v.x = *reinterpret_cast<unsigned int*>(&h0);
            v.y = *reinterpret_cast<unsigned int*>(&h1);
            ((uint2*)(g_h + (size_t)node * D))[tx] = v;
        }
    }
}

// ---------------------------------------------------------------------------
// Pull aggregation (R10 measured-best, verbatim): warp per dst node,
// lane owns 4 dims; fp16 gather, f32x2 accumulate, unroll 2.
// ---------------------------------------------------------------------------
__device__ __forceinline__ void agg_core(int node, int lane, ull& a0, ull& a1) {
    int beg = g_off[node];
    int end = beg + g_cnt[node];
    const ull* hv = (const ull*)g_h;

    int j = beg;
    for (; j + 1 < end; j += 2) {
        int s0 = __ldg(&g_csr_src[j]);
        int s1 = __ldg(&g_csr_src[j + 1]);
        float c0 = __ldg(&g_csr_coef[j]);
        float c1 = __ldg(&g_csr_coef[j + 1]);
        ull h0 = __ldg(hv + (size_t)s0 * 32 + lane);
        ull h1 = __ldg(hv + (size_t)s1 * 32 + lane);
        ull l0, u0, l1, u1;
        h4_to_f2x2(h0, l0, u0);
        h4_to_f2x2(h1, l1, u1);
        ull cp0 = pk2(c0), cp1 = pk2(c1);
        fma2(a0, cp0, l0); fma2(a1, cp0, u0);
        fma2(a0, cp1, l1); fma2(a1, cp1, u1);
    }
    if (j < end) {
        int s0 = __ldg(&g_csr_src[j]);
        float c0 = __ldg(&g_csr_coef[j]);
        ull h0 = __ldg(hv + (size_t)s0 * 32 + lane);
        ull l0, u0;
        h4_to_f2x2(h0, l0, u0);
        ull cp0 = pk2(c0);
        fma2(a0, cp0, l0); fma2(a1, cp0, u0);
    }

    // self-loop: + dinv^2 * h[node]
    float sl = g_dinv[node];
    ull slp = pk2(sl * sl);
    ull hs = hv[(size_t)node * 32 + lane];
    ull ls, us;
    h4_to_f2x2(hs, ls, us);
    fma2(a0, slp, ls); fma2(a1, slp, us);
}

__global__ void agg1_kernel(const float* __restrict__ b, int n) {
    int node = blockIdx.x * 8 + (threadIdx.x >> 5);
    int lane = threadIdx.x & 31;
    if (node >= n) return;

    ull a0 = 0ull, a1 = 0ull;
    agg_core(node, lane, a0, a1);

    if (lane == 0) g_cur[node] = 0;   // restore zero-state (last use: scatter)

    float2 p0 = unpk(a0), p1 = unpk(a1);
    float4 bias = __ldg((const float4*)b + lane);
    float4 v;
    v.x = fmaxf(p0.x + bias.x, 0.f);
    v.y = fmaxf(p0.y + bias.y, 0.f);
    v.z = fmaxf(p1.x + bias.z, 0.f);
    v.w = fmaxf(p1.y + bias.w, 0.f);
    ((float4*)g_x1)[(size_t)node * 32 + lane] = v;
}

__global__ void agg2_kernel(const float* __restrict__ b,
                            float* __restrict__ out, int n) {
    int node = blockIdx.x * 8 + (threadIdx.x >> 5);
    int lane = threadIdx.x & 31;
    if (node >= n) return;

    ull a0 = 0ull, a1 = 0ull;
    agg_core(node, lane, a0, a1);

    if (lane == 0) {
        g_cnt[node] = 0;              // restore zero-state
        if (node == 0) g_total = 0;
    }

    float2 p0 = unpk(a0), p1 = unpk(a1);
    float4 bias = __ldg((const float4*)b + lane);
    float4 v2;
    v2.x = fmaxf(p0.x + bias.x, 0.f);
    v2.y = fmaxf(p0.y + bias.y, 0.f);
    v2.z = fmaxf(p1.x + bias.z, 0.f);
    v2.w = fmaxf(p1.y + bias.w, 0.f);

    float4 v1 = ((const float4*)g_x1)[(size_t)node * 32 + lane];
    float4 lo = make_float4(v1.x, v2.x, v1.y, v2.y);
    float4 hi = make_float4(v1.z, v2.z, v1.w, v2.w);
    size_t o = (size_t)node * 64 + (size_t)lane * 2;
    ((float4*)out)[o] = lo;
    ((float4*)out)[o + 1] = hi;
}

// ---------------------------------------------------------------------------
extern "C" void kernel_launch(void* const* d_in, const int* in_sizes, int n_in,
                              void* d_out, int out_size) {
    const float* x = (const float*)d_in[0];
    const int* ei = (const int*)d_in[1];   // int32 edge_index (proven)
    const float* ew = (const float*)d_in[2];
    const float* W1 = (const float*)d_in[3];
    const float* b1 = (const float*)d_in[4];
    const float* W2 = (const float*)d_in[5];
    const float* b2 = (const float*)d_in[6];
    float* out = (float*)d_out;

    int n = in_sizes[0] / D;   // 50000
    int E = in_sizes[2];       // 800000

    static cudaStream_t s2 = nullptr;
    static cudaEvent_t evRoot = nullptr, evPrep = nullptr;
    static const float* x1_ptr = nullptr;
    if (!s2) {
        cudaStreamCreateWithFlags(&s2, cudaStreamNonBlocking);
        cudaEventCreateWithFlags(&evRoot, cudaEventDisableTiming);
        cudaEventCreateWithFlags(&evPrep, cudaEventDisableTiming);
        void* p = nullptr;
        cudaGetSymbolAddress(&p, g_x1);
        x1_ptr = (const float*)p;
    }

    int tb = 256;
    int nodeBlocks = (n + tb - 1) / tb;
    int edgeBlocks = (E + tb - 1) / tb;
    int gemmBlocks = (n + 31) / 32;
    int aggBlocks = (n + 7) / 8;

    // Fork point (R10 structure — measured best)
    cudaEventRecord(evRoot, 0);

    // [1] GEMM1 on default stream (concurrent with prep)
    gemm_kernel<<<gemmBlocks, 128>>>(x, W1, n);

    // Prep chain on s2: [2-4]
    cudaStreamWaitEvent(s2, evRoot, 0);
    deg_hist_kernel<<<edgeBlocks, tb, 0, s2>>>(ei, ew, E, n);
    offsets_kernel<<<nodeBlocks, tb, 0, s2>>>(n);
    scatter_kernel<<<edgeBlocks, tb, 0, s2>>>(ei, ew, E, n);
    cudaEventRecord(evPrep, s2);

    // Join, then sequential main path: [5-7]
    cudaStreamWaitEvent(0, evPrep, 0);
    agg1_kernel<<<aggBlocks, tb>>>(b1, n);
    gemm_kernel<<<gemmBlocks, 128>>>(x1_ptr, W2, n);
    agg2_kernel<<<aggBlocks, tb>>>(b2, out, n);
}

// round 17
// speedup vs baseline: 1.6473x; 1.5599x over previous
#include <cuda_runtime.h>
#include <cuda_fp16.h>

#define NN 50000
#define D 128
#define EE 800000
#define GB 128                 // nodes per MMA gemm block
#define LDA 136                // smem row stride (halfs): 272B, conflict-free LDSM
#define SMEM_MMA (2 * 128 * LDA * 2)   // A tile + W tile, fp16

typedef unsigned long long ull;

// Scratch (device globals: allocation-free; zero-initialized at module load;
// kernels restore zero-state after last use so graph replays see identical
// initial conditions).
__device__ __align__(16) __half g_h[NN * D];    // fp16 features (both layers)
__device__ __align__(16) float g_x1[NN * D];    // layer-1 activations (f32)
__device__ float g_deg[NN];
__device__ float g_dinv[NN];
__device__ int   g_cnt[NN];
__device__ int   g_cur[NN];
__device__ int   g_off[NN];                     // segment start (unordered)
__device__ int   g_total;                       // segment allocator
__device__ int   g_csr_src[EE];
__device__ float g_csr_coef[EE];

// ---- packed f32x2 helpers (sm_103a) ---------------------------------------
__device__ __forceinline__ ull pk2(float a) {
    ull r; asm("mov.b64 %0, {%1, %1};" : "=l"(r) : "f"(a)); return r;
}
__device__ __forceinline__ ull pkf2(float2 a) {
    ull r; asm("mov.b64 %0, {%1, %2};" : "=l"(r) : "f"(a.x), "f"(a.y)); return r;
}
__device__ __forceinline__ void fma2(ull& d, ull a, ull b) {
    asm("fma.rn.f32x2 %0, %1, %2, %0;" : "+l"(d) : "l"(a), "l"(b));
}
__device__ __forceinline__ float2 unpk(ull a) {
    float2 r; asm("mov.b64 {%0, %1}, %2;" : "=f"(r.x), "=f"(r.y) : "l"(a)); return r;
}
__device__ __forceinline__ void h4_to_f2x2(ull h, ull& lo, ull& hi) {
    unsigned int ulo = (unsigned int)h;
    unsigned int uhi = (unsigned int)(h >> 32);
    float2 flo = __half22float2(*reinterpret_cast<__half2*>(&ulo));
    float2 fhi = __half22float2(*reinterpret_cast<__half2*>(&uhi));
    lo = pkf2(flo);
    hi = pkf2(fhi);
}

__device__ __forceinline__ unsigned smem_u32(const void* p) {
    unsigned r;
    asm("{ .reg .u64 t; cvta.to.shared.u64 t, %1; cvt.u32.u64 %0, t; }"
        : "=r"(r) : "l"(p));
    return r;
}

// ---------------------------------------------------------------------------
// Prep (R10 measured-best; int32 edges proven; guards keep surprises non-UB)
// ---------------------------------------------------------------------------
__global__ void deg_hist_kernel(const int* __restrict__ ei,
                                const float* __restrict__ ew, int E, int n) {
    int e = blockIdx.x * blockDim.x + threadIdx.x;
    if (e < E) {
        int d = ei[E + e];
        if ((unsigned)d >= (unsigned)n) return;
        atomicAdd(&g_deg[d], ew[e]);
        atomicAdd(&g_cnt[d], 1);
    }
}

__global__ void offsets_kernel(int n) {
    int i = blockIdx.x * blockDim.x + threadIdx.x;
    if (i < n) {
        int cnt = g_cnt[i];
        g_off[i] = atomicAdd(&g_total, cnt);
        g_dinv[i] = rsqrtf(g_deg[i] + 1.0f);
        g_deg[i] = 0.0f;
    }
}

__global__ void scatter_kernel(const int* __restrict__ ei,
                               const float* __restrict__ ew, int E, int n) {
    int e = blockIdx.x * blockDim.x + threadIdx.x;
    if (e < E) {
        int s = ei[e];
        int d = ei[E + e];
        if ((unsigned)s >= (unsigned)n || (unsigned)d >= (unsigned)n) return;
        int pos = g_off[d] + atomicAdd(&g_cur[d], 1);
        g_csr_src[pos] = s;
        g_csr_coef[pos] = g_dinv[s] * ew[e] * g_dinv[d];
    }
}

// ---------------------------------------------------------------------------
// Tensor-core GEMM: g_h(fp16) = X(f32->fp16) * W(f32->fp16), f32 accumulate.
// Block 256 thr (8 warps), 128 nodes. mma.m16n8k16; warp owns 16 nodes x 128.
// ---------------------------------------------------------------------------
__device__ __forceinline__ void mma16816(float* c, unsigned a0, unsigned a1,
                                         unsigned a2, unsigned a3,
                                         unsigned b0, unsigned b1) {
    asm("mma.sync.aligned.m16n8k16.row.col.f32.f16.f16.f32 "
        "{%0,%1,%2,%3},{%4,%5,%6,%7},{%8,%9},{%0,%1,%2,%3};"
        : "+f"(c[0]), "+f"(c[1]), "+f"(c[2]), "+f"(c[3])
        : "r"(a0), "r"(a1), "r"(a2), "r"(a3), "r"(b0), "r"(b1));
}

__global__ void __launch_bounds__(256)
gemm_mma_kernel(const float* __restrict__ X, const float* __restrict__ Wf,
                int n) {
    extern __shared__ __half sm[];
    __half* As = sm;                 // [128][LDA]
    __half* Bs = sm + 128 * LDA;     // [128][LDA]  (W, row-major K x N)
    int t = threadIdx.x;
    int node0 = blockIdx.x * GB;

    // Fill W tile: 128x128 f32 -> fp16 (half2-packed stores)
    for (int i = t; i < 128 * 64; i += 256) {
        int k = i >> 6, c2 = i & 63;
        float2 w = __ldg((const float2*)(Wf + (size_t)k * D) + c2);
        *(__half2*)(Bs + k * LDA + c2 * 2) = __floats2half2_rn(w.x, w.y);
    }
    // Fill A tile: 128 nodes x 128 dims f32 -> fp16
    for (int i = t; i < GB * 64; i += 256) {
        int r = i >> 6, c2 = i & 63;
        float2 v = make_float2(0.f, 0.f);
        if (node0 + r < n)
            v = __ldg((const float2*)(X + (size_t)(node0 + r) * D) + c2);
        *(__half2*)(As + r * LDA + c2 * 2) = __floats2half2_rn(v.x, v.y);
    }
    __syncthreads();

    int warp = t >> 5, lane = t & 31;
    int m0 = warp * 16;

    float acc[16][4];
#pragma unroll
    for (int i = 0; i < 16; i++)
#pragma unroll
        for (int j = 0; j < 4; j++) acc[i][j] = 0.f;

    // ldmatrix lane addressing (canonical patterns)
    int a_row = m0 + (lane & 15);            // lanes 0-15: rows 0-15
    int a_col8 = (lane >> 4) << 3;           // lanes 16-31: +8 columns
    int b_row = lane & 15;                   // rows k0..k0+15 (x2 uses lanes 0-15)

#pragma unroll
    for (int ks = 0; ks < 8; ks++) {
        int k0 = ks * 16;
        unsigned a0, a1, a2, a3;
        unsigned aaddr = smem_u32(As + (size_t)a_row * LDA + k0 + a_col8);
        asm volatile("ldmatrix.sync.aligned.m8n8.x4.shared.b16 {%0,%1,%2,%3},[%4];"
                     : "=r"(a0), "=r"(a1), "=r"(a2), "=r"(a3) : "r"(aaddr));

        unsigned bbase = smem_u32(Bs + (size_t)(k0 + b_row) * LDA);
#pragma unroll
        for (int nt = 0; nt < 16; nt++) {
            unsigned b0, b1;
            asm volatile("ldmatrix.sync.aligned.m8n8.x2.trans.shared.b16 {%0,%1},[%2];"
                         : "=r"(b0), "=r"(b1) : "r"(bbase + nt * 16));
            mma16816(acc[nt], a0, a1, a2, a3, b0, b1);
        }
    }

    // Epilogue: c-fragment layout (row0=l/4, row1=l/4+8; col=(l%4)*2) -> half2
    int row0 = m0 + (lane >> 2);
    int colb = (lane & 3) * 2;
#pragma unroll
    for (int nt = 0; nt < 16; nt++) {
        int col = nt * 8 + colb;
        int nodeA = node0 + row0;
        int nodeB = nodeA + 8;
        if (nodeA < n)
            *(__half2*)(g_h + (size_t)nodeA * D + col) =
                __floats2half2_rn(acc[nt][0], acc[nt][1]);
        if (nodeB < n)
            *(__half2*)(g_h + (size_t)nodeB * D + col) =
                __floats2half2_rn(acc[nt][2], acc[nt][3]);
    }
}

// ---------------------------------------------------------------------------
// Pull aggregation (R10 measured-best, verbatim): warp per dst node,
// lane owns 4 dims; fp16 gather, f32x2 accumulate, unroll 2.
// ---------------------------------------------------------------------------
__device__ __forceinline__ void agg_core(int node, int lane, ull& a0, ull& a1) {
    int beg = g_off[node];
    int end = beg + g_cnt[node];
    const ull* hv = (const ull*)g_h;

    int j = beg;
    for (; j + 1 < end; j += 2) {
        int s0 = __ldg(&g_csr_src[j]);
        int s1 = __ldg(&g_csr_src[j + 1]);
        float c0 = __ldg(&g_csr_coef[j]);
        float c1 = __ldg(&g_csr_coef[j + 1]);
        ull h0 = __ldg(hv + (size_t)s0 * 32 + lane);
        ull h1 = __ldg(hv + (size_t)s1 * 32 + lane);
        ull l0, u0, l1, u1;
        h4_to_f2x2(h0, l0, u0);
        h4_to_f2x2(h1, l1, u1);
        ull cp0 = pk2(c0), cp1 = pk2(c1);
        fma2(a0, cp0, l0); fma2(a1, cp0, u0);
        fma2(a0, cp1, l1); fma2(a1, cp1, u1);
    }
    if (j < end) {
        int s0 = __ldg(&g_csr_src[j]);
        float c0 = __ldg(&g_csr_coef[j]);
        ull h0 = __ldg(hv + (size_t)s0 * 32 + lane);
        ull l0, u0;
        h4_to_f2x2(h0, l0, u0);
        ull cp0 = pk2(c0);
        fma2(a0, cp0, l0); fma2(a1, cp0, u0);
    }

    float sl = g_dinv[node];
    ull slp = pk2(sl * sl);
    ull hs = hv[(size_t)node * 32 + lane];
    ull ls, us;
    h4_to_f2x2(hs, ls, us);
    fma2(a0, slp, ls); fma2(a1, slp, us);
}

__global__ void agg1_kernel(const float* __restrict__ b, int n) {
    int node = blockIdx.x * 8 + (threadIdx.x >> 5);
    int lane = threadIdx.x & 31;
    if (node >= n) return;

    ull a0 = 0ull, a1 = 0ull;
    agg_core(node, lane, a0, a1);

    if (lane == 0) g_cur[node] = 0;   // restore zero-state

    float2 p0 = unpk(a0), p1 = unpk(a1);
    float4 bias = __ldg((const float4*)b + lane);
    float4 v;
    v.x = fmaxf(p0.x + bias.x, 0.f);
    v.y = fmaxf(p0.y + bias.y, 0.f);
    v.z = fmaxf(p1.x + bias.z, 0.f);
    v.w = fmaxf(p1.y + bias.w, 0.f);
    ((float4*)g_x1)[(size_t)node * 32 + lane] = v;
}

__global__ void agg2_kernel(const float* __restrict__ b,
                            float* __restrict__ out, int n) {
    int node = blockIdx.x * 8 + (threadIdx.x >> 5);
    int lane = threadIdx.x & 31;
    if (node >= n) return;

    ull a0 = 0ull, a1 = 0ull;
    agg_core(node, lane, a0, a1);

    if (lane == 0) {
        g_cnt[node] = 0;              // restore zero-state
        if (node == 0) g_total = 0;
    }

    float2 p0 = unpk(a0), p1 = unpk(a1);
    float4 bias = __ldg((const float4*)b + lane);
    float4 v2;
    v2.x = fmaxf(p0.x + bias.x, 0.f);
    v2.y = fmaxf(p0.y + bias.y, 0.f);
    v2.z = fmaxf(p1.x + bias.z, 0.f);
    v2.w = fmaxf(p1.y + bias.w, 0.f);

    float4 v1 = ((const float4*)g_x1)[(size_t)node * 32 + lane];
    float4 lo = make_float4(v1.x, v2.x, v1.y, v2.y);
    float4 hi = make_float4(v1.z, v2.z, v1.w, v2.w);
    size_t o = (size_t)node * 64 + (size_t)lane * 2;
    ((float4*)out)[o] = lo;
    ((float4*)out)[o + 1] = hi;
}

// ---------------------------------------------------------------------------
extern "C" void kernel_launch(void* const* d_in, const int* in_sizes, int n_in,
                              void* d_out, int out_size) {
    const float* x = (const float*)d_in[0];
    const int* ei = (const int*)d_in[1];   // int32 edge_index (proven)
    const float* ew = (const float*)d_in[2];
    const float* W1 = (const float*)d_in[3];
    const float* b1 = (const float*)d_in[4];
    const float* W2 = (const float*)d_in[5];
    const float* b2 = (const float*)d_in[6];
    float* out = (float*)d_out;

    int n = in_sizes[0] / D;   // 50000
    int E = in_sizes[2];       // 800000

    static cudaStream_t s2 = nullptr;
    static cudaEvent_t evRoot = nullptr, evPrep = nullptr;
    static const float* x1_ptr = nullptr;
    if (!s2) {
        cudaStreamCreateWithFlags(&s2, cudaStreamNonBlocking);
        cudaEventCreateWithFlags(&evRoot, cudaEventDisableTiming);
        cudaEventCreateWithFlags(&evPrep, cudaEventDisableTiming);
        void* p = nullptr;
        cudaGetSymbolAddress(&p, g_x1);
        x1_ptr = (const float*)p;
        cudaFuncSetAttribute(gemm_mma_kernel,
                             cudaFuncAttributeMaxDynamicSharedMemorySize,
                             SMEM_MMA);
    }

    int tb = 256;
    int nodeBlocks = (n + tb - 1) / tb;
    int edgeBlocks = (E + tb - 1) / tb;
    int gemmBlocks = (n + GB - 1) / GB;
    int aggBlocks = (n + 7) / 8;

    // Fork point (R10 structure — measured best)
    cudaEventRecord(evRoot, 0);

    // [1] GEMM1 (tensor cores) on default stream, concurrent with prep
    gemm_mma_kernel<<<gemmBlocks, 256, SMEM_MMA>>>(x, W1, n);

    // Prep chain on s2: [2-4]
    cudaStreamWaitEvent(s2, evRoot, 0);
    deg_hist_kernel<<<edgeBlocks, tb, 0, s2>>>(ei, ew, E, n);
    offsets_kernel<<<nodeBlocks, tb, 0, s2>>>(n);
    scatter_kernel<<<edgeBlocks, tb, 0, s2>>>(ei, ew, E, n);
    cudaEventRecord(evPrep, s2);

    // Join, then sequential main path: [5-7]
    cudaStreamWaitEvent(0, evPrep, 0);
    agg1_kernel<<<aggBlocks, tb>>>(b1, n);
    gemm_mma_kernel<<<gemmBlocks, 256, SMEM_MMA>>>(x1_ptr, W2, n);
    agg2_kernel<<<aggBlocks, tb>>>(b2, out, n);
}